// round 3
// baseline (speedup 1.0000x reference)
#include <cuda_runtime.h>
#include <math_constants.h>

#define BB   2
#define NN   32768
#define NCC  1024
#define SS   32
#define MM   (NCC*SS)          // 32768

#define NN_WARPS  8            // warps per block in k_nn
#define QPW       8            // queries per warp
#define QPB       (NN_WARPS*QPW)   // 64 queries per block

// Scratch (no allocations allowed) ------------------------------------------
__device__ float4       g_xyzp [BB*NN];   // (x,y,z,|p|^2)
__device__ float4       g_ctr  [BB*NCC];  // (x,y,z,|c|^2)
__device__ int          g_assign[BB*NN];  // nearest-center id per xyz point
__device__ int          g_cnt [BB*NCC];
__device__ int          g_start[BB*NCC];  // global exclusive prefix over counts
__device__ int          g_cur [BB*NCC];   // scatter cursor
__device__ unsigned int g_rmax[BB*NCC];   // max member distance (float bits)
__device__ float4       g_psort[BB*NN];   // xyz points sorted by (b, cluster)
__device__ float        g_mind[BB*MM];    // best squared distance per sphere point
__device__ float        g_acc[4];

// ---------------------------------------------------------------------------
__device__ __forceinline__ float warpMin(float v) {
    #pragma unroll
    for (int o = 16; o > 0; o >>= 1)
        v = fminf(v, __shfl_xor_sync(0xffffffffu, v, o));
    return v;
}

__inline__ __device__ float blockReduceSum(float v) {
    __shared__ float sw[32];
    #pragma unroll
    for (int o = 16; o > 0; o >>= 1) v += __shfl_down_sync(0xffffffffu, v, o);
    int lane = threadIdx.x & 31, w = threadIdx.x >> 5;
    if (lane == 0) sw[w] = v;
    __syncthreads();
    int nw = blockDim.x >> 5;
    v = (threadIdx.x < nw) ? sw[threadIdx.x] : 0.0f;
    if (w == 0) {
        #pragma unroll
        for (int o = 16; o > 0; o >>= 1) v += __shfl_down_sync(0xffffffffu, v, o);
    }
    return v;
}

// Pack inputs + init scratch --------------------------------------------------
__global__ void k_prep(const float* __restrict__ xyz, const float* __restrict__ ctr) {
    int i = blockIdx.x * blockDim.x + threadIdx.x;
    if (i < BB*NN) {
        float x = xyz[3*i+0], y = xyz[3*i+1], z = xyz[3*i+2];
        g_xyzp[i] = make_float4(x, y, z, x*x + y*y + z*z);
    }
    if (i < BB*NCC) {
        float x = ctr[3*i+0], y = ctr[3*i+1], z = ctr[3*i+2];
        g_ctr[i] = make_float4(x, y, z, x*x + y*y + z*z);
        g_cnt[i] = 0;
        g_rmax[i] = 0u;
    }
    if (i < 4) g_acc[i] = 0.0f;
}

// Part 1: xyz -> nearest center. Loss contrib + cluster assignment ------------
__global__ void k_p2c(const float* __restrict__ radius) {
    __shared__ float4 shc[NCC];
    const int b = blockIdx.y;
    const int n = blockIdx.x * blockDim.x + threadIdx.x;
    for (int i = threadIdx.x; i < NCC; i += blockDim.x)
        shc[i] = g_ctr[b*NCC + i];
    __syncthreads();

    float4 q = g_xyzp[b*NN + n];
    float ax = -2.0f*q.x, ay = -2.0f*q.y, az = -2.0f*q.z;
    float tmin = CUDART_INF_F;
    int idx = 0;
    #pragma unroll 4
    for (int c = 0; c < NCC; ++c) {
        float4 p = shc[c];
        float t = fmaf(ax, p.x, p.w);
        t = fmaf(ay, p.y, t);
        t = fmaf(az, p.z, t);
        if (t < tmin) { tmin = t; idx = c; }   // strict < : first-min == jnp.argmin
    }
    float cd = sqrtf(fmaxf(tmin + q.w, 1e-12f));
    float contrib = fmaxf(cd - radius[b*NCC + idx], 0.0f); // == |min(r-cd,0)|
    float s = blockReduceSum(contrib);
    if (threadIdx.x == 0) atomicAdd(&g_acc[b], s);

    // cluster structure
    g_assign[b*NN + n] = idx;
    atomicAdd(&g_cnt[b*NCC + idx], 1);
    atomicMax(&g_rmax[b*NCC + idx], __float_as_uint(cd));  // cd >= 0
}

// Exclusive prefix over all BB*NCC counts (one block, 1024 threads) ----------
__global__ void k_scan() {
    __shared__ int sa[1024], sb[1024];
    const int t = threadIdx.x;
    int c0 = g_cnt[2*t], c1 = g_cnt[2*t+1];
    sa[t] = c0 + c1;
    int* src = sa; int* dst = sb;
    #pragma unroll
    for (int off = 1; off < 1024; off <<= 1) {
        __syncthreads();
        int v = src[t];
        if (t >= off) v += src[t - off];
        dst[t] = v;
        int* tmp = src; src = dst; dst = tmp;
    }
    __syncthreads();
    int incl = src[t];
    int excl = incl - (c0 + c1);
    g_start[2*t]   = excl;       g_cur[2*t]   = excl;
    g_start[2*t+1] = excl + c0;  g_cur[2*t+1] = excl + c0;
}

// Scatter xyz points into cluster-sorted order --------------------------------
__global__ void k_scatter() {
    int i = blockIdx.x * blockDim.x + threadIdx.x;
    if (i >= BB*NN) return;
    int b = i / NN;
    int bc = b*NCC + g_assign[i];
    int pos = atomicAdd(&g_cur[bc], 1);
    g_psort[pos] = g_xyzp[i];
}

// Part 2: sphere point -> exact NN via center-cluster pruning. 1 warp/query. --
__global__ void __launch_bounds__(32*NN_WARPS)
k_nn(const float* __restrict__ sp) {
    __shared__ float4 shc[NCC];   // centers
    __shared__ int2   shcs[NCC];  // (start, count)
    __shared__ float  shr[NCC];   // padded cluster radius
    const int tid  = threadIdx.x;
    const int lane = tid & 31;
    const int warp = tid >> 5;
    const int qblock = blockIdx.x * QPB;
    const int b = qblock / MM;    // QPB divides MM, block never straddles batches

    for (int i = tid; i < NCC; i += 32*NN_WARPS) {
        shc[i]  = g_ctr[b*NCC + i];
        shcs[i] = make_int2(g_start[b*NCC + i], g_cnt[b*NCC + i]);
        shr[i]  = __uint_as_float(g_rmax[b*NCC + i]) * 1.000002f + 1e-6f;
    }
    __syncthreads();

    for (int qi = 0; qi < QPW; ++qi) {
        const int q = qblock + warp*QPW + qi;       // global sphere-point index
        const float* sq = sp + (long long)q * 3;
        float qx = sq[0], qy = sq[1], qz = sq[2];   // warp-broadcast loads
        float ax = -2.0f*qx, ay = -2.0f*qy, az = -2.0f*qz;
        float qw = qx*qx + qy*qy + qz*qz;

        // Phase A: squared distance to all 1024 centers (lane l owns k*32+l)
        float dsq[32];
        float tmin = CUDART_INF_F; int tidx = 0;
        #pragma unroll
        for (int k = 0; k < 32; ++k) {
            float4 c = shc[k*32 + lane];
            float t = fmaf(ax, c.x, c.w);
            t = fmaf(ay, c.y, t);
            t = fmaf(az, c.z, t);
            dsq[k] = t + qw;
            if (t < tmin) { tmin = t; tidx = k*32 + lane; }
        }
        // warp argmin -> seed cluster
        #pragma unroll
        for (int o = 16; o > 0; o >>= 1) {
            float ot = __shfl_down_sync(0xffffffffu, tmin, o);
            int   oi = __shfl_down_sync(0xffffffffu, tidx, o);
            if (ot < tmin) { tmin = ot; tidx = oi; }
        }
        const int cidx0 = __shfl_sync(0xffffffffu, tidx, 0);

        // Phase B: seed best from nearest center's cluster
        float lmin = CUDART_INF_F;
        {
            int2 sc = shcs[cidx0];
            for (int o = lane; o < sc.y; o += 32) {
                float4 p = g_psort[sc.x + o];
                float t = fmaf(ax, p.x, p.w);
                t = fmaf(ay, p.y, t);
                t = fmaf(az, p.z, t);
                lmin = fminf(lmin, t + qw);
            }
        }
        float best2 = warpMin(lmin);
        float best  = sqrtf(fmaxf(best2, 0.0f));

        // Scan remaining clusters with triangle-inequality pruning (exact)
        #pragma unroll
        for (int k = 0; k < 32; ++k) {
            const int cid_l = k*32 + lane;
            int cnt_l = shcs[cid_l].y;
            float thr = best + shr[cid_l];
            bool pred = (cnt_l > 0) && (cid_l != cidx0) && (dsq[k] < thr*thr);
            unsigned mask = __ballot_sync(0xffffffffu, pred);
            while (mask) {
                int s = __ffs(mask) - 1; mask &= mask - 1;
                int cid = k*32 + s;
                float dq  = __shfl_sync(0xffffffffu, dsq[k], s);
                float th2 = best + shr[cid];           // re-check with current best
                if (dq < th2*th2) {
                    int2 sc = shcs[cid];
                    for (int o = lane; o < sc.y; o += 32) {
                        float4 p = g_psort[sc.x + o];
                        float t = fmaf(ax, p.x, p.w);
                        t = fmaf(ay, p.y, t);
                        t = fmaf(az, p.z, t);
                        lmin = fminf(lmin, t + qw);
                    }
                    best2 = warpMin(lmin);
                    best  = sqrtf(fmaxf(best2, 0.0f));
                }
            }
        }
        if (lane == 0) g_mind[q] = fmaxf(best2, 0.0f);
    }
}

// Epilogue: max over S per center, sum over centers ---------------------------
__global__ void k_c2p() {
    const int b = blockIdx.y;
    const int c = blockIdx.x * blockDim.x + threadIdx.x;
    const float* base = g_mind + b*MM + c*SS;
    float mx = 0.0f;
    #pragma unroll
    for (int s = 0; s < SS; ++s)
        mx = fmaxf(mx, sqrtf(fmaxf(base[s], 1e-12f)));
    float s = blockReduceSum(mx);
    if (threadIdx.x == 0) atomicAdd(&g_acc[2 + b], s);
}

// Final scalar ----------------------------------------------------------------
__global__ void k_final(float* out) {
    float r = 0.0f;
    #pragma unroll
    for (int b = 0; b < BB; ++b)
        r += g_acc[b] * (1.0f/NN) + g_acc[2 + b] * (1.0f/NCC);
    out[0] = r * (1.0f/BB);
}

// ---------------------------------------------------------------------------
extern "C" void kernel_launch(void* const* d_in, const int* in_sizes, int n_in,
                              void* d_out, int out_size) {
    const float* centers = (const float*)d_in[0];
    const float* radius  = (const float*)d_in[1];
    const float* xyz     = (const float*)d_in[2];
    const float* sp      = (const float*)d_in[3];
    float* out = (float*)d_out;

    k_prep<<<(BB*NN + 255)/256, 256>>>(xyz, centers);
    k_p2c<<<dim3(NN/256, BB), 256>>>(radius);
    k_scan<<<1, 1024>>>();
    k_scatter<<<(BB*NN)/256, 256>>>();
    k_nn<<<(BB*MM)/QPB, 32*NN_WARPS>>>(sp);
    k_c2p<<<dim3(NCC/256, BB), 256>>>();
    k_final<<<1, 1>>>(out);
}

// round 4
// speedup vs baseline: 2.6609x; 2.6609x over previous
#include <cuda_runtime.h>
#include <math_constants.h>

#define BB   2
#define NN   32768
#define NCC  1024
#define SS   32
#define MM   (NCC*SS)          // 32768

#define NN_WARPS  8            // warps per block in k_nn
#define QPW       8            // queries per warp
#define QPB       (NN_WARPS*QPW)   // 64 queries per block

// Scratch (no allocations allowed) ------------------------------------------
__device__ float4       g_xyzp [BB*NN];   // (x,y,z,|p|^2)
__device__ float4       g_ctr  [BB*NCC];  // (x,y,z,|c|^2)
__device__ int          g_assign[BB*NN];  // nearest-center id per xyz point
__device__ int          g_cnt [BB*NCC];
__device__ int          g_start[BB*NCC];  // global exclusive prefix over counts
__device__ int          g_cur [BB*NCC];   // scatter cursor
__device__ unsigned int g_rmax[BB*NCC];   // max member distance (float bits)
__device__ float4       g_psort[BB*NN];   // xyz points sorted by (b, cluster)
__device__ float        g_mind[BB*MM];    // best squared distance per sphere point
__device__ float        g_acc[4];

// ---------------------------------------------------------------------------
__device__ __forceinline__ float warpMin(float v) {
    #pragma unroll
    for (int o = 16; o > 0; o >>= 1)
        v = fminf(v, __shfl_xor_sync(0xffffffffu, v, o));
    return v;
}

__inline__ __device__ float blockReduceSum(float v) {
    __shared__ float sw[32];
    #pragma unroll
    for (int o = 16; o > 0; o >>= 1) v += __shfl_down_sync(0xffffffffu, v, o);
    int lane = threadIdx.x & 31, w = threadIdx.x >> 5;
    if (lane == 0) sw[w] = v;
    __syncthreads();
    int nw = blockDim.x >> 5;
    v = (threadIdx.x < nw) ? sw[threadIdx.x] : 0.0f;
    if (w == 0) {
        #pragma unroll
        for (int o = 16; o > 0; o >>= 1) v += __shfl_down_sync(0xffffffffu, v, o);
    }
    return v;
}

// Pack inputs + init scratch --------------------------------------------------
__global__ void k_prep(const float* __restrict__ xyz, const float* __restrict__ ctr) {
    int i = blockIdx.x * blockDim.x + threadIdx.x;
    if (i < BB*NN) {
        float x = xyz[3*i+0], y = xyz[3*i+1], z = xyz[3*i+2];
        g_xyzp[i] = make_float4(x, y, z, x*x + y*y + z*z);
    }
    if (i < BB*NCC) {
        float x = ctr[3*i+0], y = ctr[3*i+1], z = ctr[3*i+2];
        g_ctr[i] = make_float4(x, y, z, x*x + y*y + z*z);
        g_cnt[i] = 0;
        g_rmax[i] = 0u;
    }
    if (i < 4) g_acc[i] = 0.0f;
}

// Part 1: xyz -> nearest center. Loss contrib + cluster assignment ------------
__global__ void k_p2c(const float* __restrict__ radius) {
    __shared__ float4 shc[NCC];
    const int b = blockIdx.y;
    const int n = blockIdx.x * blockDim.x + threadIdx.x;
    for (int i = threadIdx.x; i < NCC; i += blockDim.x)
        shc[i] = g_ctr[b*NCC + i];
    __syncthreads();

    float4 q = g_xyzp[b*NN + n];
    float ax = -2.0f*q.x, ay = -2.0f*q.y, az = -2.0f*q.z;
    float tmin = CUDART_INF_F;
    int idx = 0;
    #pragma unroll 4
    for (int c = 0; c < NCC; ++c) {
        float4 p = shc[c];
        float t = fmaf(ax, p.x, p.w);
        t = fmaf(ay, p.y, t);
        t = fmaf(az, p.z, t);
        if (t < tmin) { tmin = t; idx = c; }   // strict < : first-min == jnp.argmin
    }
    float cd = sqrtf(fmaxf(tmin + q.w, 1e-12f));
    float contrib = fmaxf(cd - radius[b*NCC + idx], 0.0f); // == |min(r-cd,0)|
    float s = blockReduceSum(contrib);
    if (threadIdx.x == 0) atomicAdd(&g_acc[b], s);

    // cluster structure
    g_assign[b*NN + n] = idx;
    atomicAdd(&g_cnt[b*NCC + idx], 1);
    atomicMax(&g_rmax[b*NCC + idx], __float_as_uint(cd));  // cd >= 0
}

// Exclusive prefix over all BB*NCC counts (one block, 1024 threads) ----------
__global__ void k_scan() {
    __shared__ int sa[1024], sb[1024];
    const int t = threadIdx.x;
    int c0 = g_cnt[2*t], c1 = g_cnt[2*t+1];
    sa[t] = c0 + c1;
    int* src = sa; int* dst = sb;
    #pragma unroll
    for (int off = 1; off < 1024; off <<= 1) {
        __syncthreads();
        int v = src[t];
        if (t >= off) v += src[t - off];
        dst[t] = v;
        int* tmp = src; src = dst; dst = tmp;
    }
    __syncthreads();
    int incl = src[t];
    int excl = incl - (c0 + c1);
    g_start[2*t]   = excl;       g_cur[2*t]   = excl;
    g_start[2*t+1] = excl + c0;  g_cur[2*t+1] = excl + c0;
}

// Scatter xyz points into cluster-sorted order --------------------------------
__global__ void k_scatter() {
    int i = blockIdx.x * blockDim.x + threadIdx.x;
    if (i >= BB*NN) return;
    int b = i / NN;
    int bc = b*NCC + g_assign[i];
    int pos = atomicAdd(&g_cur[bc], 1);
    g_psort[pos] = g_xyzp[i];
}

// Part 2: sphere point -> exact NN via center-cluster pruning. 1 warp/query. --
// Lean inner loop: fixed seed threshold, single final reduction.
__global__ void __launch_bounds__(32*NN_WARPS)
k_nn(const float* __restrict__ sp) {
    __shared__ float4 shc[NCC];   // centers (x,y,z,|c|^2)
    __shared__ int2   shcs[NCC];  // (start, count)
    __shared__ float  shr[NCC];   // padded cluster radius
    const int tid  = threadIdx.x;
    const int lane = tid & 31;
    const int warp = tid >> 5;
    const int qblock = blockIdx.x * QPB;
    const int b = qblock / MM;    // QPB divides MM, block never straddles batches

    for (int i = tid; i < NCC; i += 32*NN_WARPS) {
        shc[i]  = g_ctr[b*NCC + i];
        shcs[i] = make_int2(g_start[b*NCC + i], g_cnt[b*NCC + i]);
        shr[i]  = __uint_as_float(g_rmax[b*NCC + i]) * 1.000002f + 1e-6f;
    }
    __syncthreads();

    const float4* __restrict__ pts = g_psort;

    for (int qi = 0; qi < QPW; ++qi) {
        const int q = qblock + warp*QPW + qi;       // global sphere-point index
        const float* sq = sp + (long long)q * 3;
        float qx = sq[0], qy = sq[1], qz = sq[2];   // warp-broadcast loads
        float ax = -2.0f*qx, ay = -2.0f*qy, az = -2.0f*qz;
        float qw = qx*qx + qy*qy + qz*qz;

        // Phase A: t = |c|^2 - 2 q.c for all 1024 centers (lane owns k*32+lane)
        float dsq[32];
        float tmin = CUDART_INF_F; int tidx = 0;
        #pragma unroll
        for (int k = 0; k < 32; ++k) {
            const int cid = k*32 + lane;
            float4 c = shc[cid];
            float t = fmaf(ax, c.x, c.w);
            t = fmaf(ay, c.y, t);
            t = fmaf(az, c.z, t);
            dsq[k] = t;
            float tm = (shcs[cid].y > 0) ? t : CUDART_INF_F;  // seed must be non-empty
            if (tm < tmin) { tmin = tm; tidx = cid; }
        }
        // warp argmin -> seed cluster
        #pragma unroll
        for (int o = 16; o > 0; o >>= 1) {
            float ot = __shfl_down_sync(0xffffffffu, tmin, o);
            int   oi = __shfl_down_sync(0xffffffffu, tidx, o);
            if (ot < tmin) { tmin = ot; tidx = oi; }
        }
        const int cidx0 = __shfl_sync(0xffffffffu, tidx, 0);

        // Phase B: seed best from nearest non-empty cluster
        float lmin = CUDART_INF_F;
        {
            int2 sc = shcs[cidx0];
            for (int o = lane; o < sc.y; o += 32) {
                float4 p = pts[sc.x + o];
                float t = fmaf(ax, p.x, p.w);
                t = fmaf(ay, p.y, t);
                t = fmaf(az, p.z, t);
                lmin = fminf(lmin, t);
            }
        }
        const float best = sqrtf(fmaxf(warpMin(lmin) + qw, 0.0f));  // seed distance

        // Phase C: scan all clusters admitted by the FIXED seed threshold.
        // Exact: seed best >= true best, so this admits a superset.
        #pragma unroll
        for (int k = 0; k < 32; ++k) {
            const int cid_l = k*32 + lane;
            float thr = best + shr[cid_l];
            bool pred = (shcs[cid_l].y > 0) && (cid_l != cidx0)
                        && (dsq[k] + qw < thr*thr);
            unsigned mask = __ballot_sync(0xffffffffu, pred);
            while (mask) {
                int s = __ffs(mask) - 1; mask &= mask - 1;
                int2 sc = shcs[k*32 + s];           // uniform -> broadcast
                for (int o = lane; o < sc.y; o += 32) {
                    float4 p = pts[sc.x + o];
                    float t = fmaf(ax, p.x, p.w);
                    t = fmaf(ay, p.y, t);
                    t = fmaf(az, p.z, t);
                    lmin = fminf(lmin, t);
                }
            }
        }
        float best2 = warpMin(lmin) + qw;
        if (lane == 0) g_mind[q] = fmaxf(best2, 0.0f);
    }
}

// Epilogue: one warp per center: max over S, then sum over centers ------------
__global__ void k_c2p() {
    const int lane = threadIdx.x & 31;
    const int wid  = (blockIdx.x * blockDim.x + threadIdx.x) >> 5;  // 0..BB*NCC-1
    float v = sqrtf(fmaxf(g_mind[wid*SS + lane], 1e-12f));
    #pragma unroll
    for (int o = 16; o > 0; o >>= 1)
        v = fmaxf(v, __shfl_xor_sync(0xffffffffu, v, o));
    if (lane == 0) atomicAdd(&g_acc[2 + wid/NCC], v);
}

// Final scalar ----------------------------------------------------------------
__global__ void k_final(float* out) {
    float r = 0.0f;
    #pragma unroll
    for (int b = 0; b < BB; ++b)
        r += g_acc[b] * (1.0f/NN) + g_acc[2 + b] * (1.0f/NCC);
    out[0] = r * (1.0f/BB);
}

// ---------------------------------------------------------------------------
extern "C" void kernel_launch(void* const* d_in, const int* in_sizes, int n_in,
                              void* d_out, int out_size) {
    const float* centers = (const float*)d_in[0];
    const float* radius  = (const float*)d_in[1];
    const float* xyz     = (const float*)d_in[2];
    const float* sp      = (const float*)d_in[3];
    float* out = (float*)d_out;

    k_prep<<<(BB*NN + 255)/256, 256>>>(xyz, centers);
    k_p2c<<<dim3(NN/256, BB), 256>>>(radius);
    k_scan<<<1, 1024>>>();
    k_scatter<<<(BB*NN)/256, 256>>>();
    k_nn<<<(BB*MM)/QPB, 32*NN_WARPS>>>(sp);
    k_c2p<<<dim3((BB*NCC*32)/256), 256>>>();
    k_final<<<1, 1>>>(out);
}

// round 5
// speedup vs baseline: 4.2042x; 1.5800x over previous
#include <cuda_runtime.h>
#include <math_constants.h>

#define BB   2
#define NN   32768
#define NCC  1024
#define SS   32
#define MM   (NCC*SS)          // 32768

#define NN_WARPS  8            // warps per block in k_nn
#define QPW       8            // queries per warp
#define QPB       (NN_WARPS*QPW)   // 64 queries per block

// Scratch (no allocations allowed) ------------------------------------------
__device__ float4       g_xyzp [BB*NN];   // (x,y,z,|p|^2)
__device__ float4       g_ctr  [BB*NCC];  // (x,y,z,|c|^2)
__device__ int          g_assign[BB*NN];  // nearest-center id per xyz point
__device__ int          g_cnt [BB*NCC];
__device__ int          g_start[BB*NCC];  // global exclusive prefix over counts
__device__ int          g_cur [BB*NCC];   // scatter cursor
__device__ unsigned int g_rmax[BB*NCC];   // max member distance (float bits)
__device__ float4       g_psort[BB*NN];   // xyz points sorted by (b, cluster)
__device__ float        g_mind[BB*MM];    // best squared distance per sphere point
__device__ float        g_acc[4];

// ---------------------------------------------------------------------------
__device__ __forceinline__ float warpMin(float v) {
    #pragma unroll
    for (int o = 16; o > 0; o >>= 1)
        v = fminf(v, __shfl_xor_sync(0xffffffffu, v, o));
    return v;
}

__inline__ __device__ float blockReduceSum(float v) {
    __shared__ float sw[32];
    #pragma unroll
    for (int o = 16; o > 0; o >>= 1) v += __shfl_down_sync(0xffffffffu, v, o);
    int lane = threadIdx.x & 31, w = threadIdx.x >> 5;
    if (lane == 0) sw[w] = v;
    __syncthreads();
    int nw = blockDim.x >> 5;
    v = (threadIdx.x < nw) ? sw[threadIdx.x] : 0.0f;
    if (w == 0) {
        #pragma unroll
        for (int o = 16; o > 0; o >>= 1) v += __shfl_down_sync(0xffffffffu, v, o);
    }
    return v;
}

// Pack inputs + init scratch --------------------------------------------------
__global__ void k_prep(const float* __restrict__ xyz, const float* __restrict__ ctr) {
    int i = blockIdx.x * blockDim.x + threadIdx.x;
    if (i < BB*NN) {
        float x = xyz[3*i+0], y = xyz[3*i+1], z = xyz[3*i+2];
        g_xyzp[i] = make_float4(x, y, z, x*x + y*y + z*z);
    }
    if (i < BB*NCC) {
        float x = ctr[3*i+0], y = ctr[3*i+1], z = ctr[3*i+2];
        g_ctr[i] = make_float4(x, y, z, x*x + y*y + z*z);
        g_cnt[i] = 0;
        g_rmax[i] = 0u;
    }
    if (i < 4) g_acc[i] = 0.0f;
}

// Part 1: xyz -> nearest center. Loss contrib + cluster assignment ------------
__global__ void k_p2c(const float* __restrict__ radius) {
    __shared__ float4 shc[NCC];
    const int b = blockIdx.y;
    const int n = blockIdx.x * blockDim.x + threadIdx.x;
    for (int i = threadIdx.x; i < NCC; i += blockDim.x)
        shc[i] = g_ctr[b*NCC + i];
    __syncthreads();

    float4 q = g_xyzp[b*NN + n];
    float ax = -2.0f*q.x, ay = -2.0f*q.y, az = -2.0f*q.z;
    float tmin = CUDART_INF_F;
    int idx = 0;
    #pragma unroll 4
    for (int c = 0; c < NCC; ++c) {
        float4 p = shc[c];
        float t = fmaf(ax, p.x, p.w);
        t = fmaf(ay, p.y, t);
        t = fmaf(az, p.z, t);
        if (t < tmin) { tmin = t; idx = c; }   // strict < : first-min == jnp.argmin
    }
    float cd = sqrtf(fmaxf(tmin + q.w, 1e-12f));
    float contrib = fmaxf(cd - radius[b*NCC + idx], 0.0f); // == |min(r-cd,0)|
    float s = blockReduceSum(contrib);
    if (threadIdx.x == 0) atomicAdd(&g_acc[b], s);

    g_assign[b*NN + n] = idx;
    atomicAdd(&g_cnt[b*NCC + idx], 1);
    atomicMax(&g_rmax[b*NCC + idx], __float_as_uint(cd));  // cd >= 0
}

// Exclusive prefix over all BB*NCC counts (one block, 1024 threads) ----------
__global__ void k_scan() {
    __shared__ int sa[1024], sb[1024];
    const int t = threadIdx.x;
    int c0 = g_cnt[2*t], c1 = g_cnt[2*t+1];
    sa[t] = c0 + c1;
    int* src = sa; int* dst = sb;
    #pragma unroll
    for (int off = 1; off < 1024; off <<= 1) {
        __syncthreads();
        int v = src[t];
        if (t >= off) v += src[t - off];
        dst[t] = v;
        int* tmp = src; src = dst; dst = tmp;
    }
    __syncthreads();
    int incl = src[t];
    int excl = incl - (c0 + c1);
    g_start[2*t]   = excl;       g_cur[2*t]   = excl;
    g_start[2*t+1] = excl + c0;  g_cur[2*t+1] = excl + c0;
}

// Scatter xyz points into cluster-sorted order --------------------------------
__global__ void k_scatter() {
    int i = blockIdx.x * blockDim.x + threadIdx.x;
    if (i >= BB*NN) return;
    int b = i / NN;
    int bc = b*NCC + g_assign[i];
    int pos = atomicAdd(&g_cur[bc], 1);
    g_psort[pos] = g_xyzp[i];
}

// Scan helper: distance term for one candidate cluster chunk (predicated) -----
__device__ __forceinline__ float candTerm(const float4* __restrict__ pts,
                                          int startv, int cnt, int o,
                                          float ax, float ay, float az) {
    if (o < cnt) {
        float4 p = pts[startv + o];
        float t = fmaf(ax, p.x, p.w);
        t = fmaf(ay, p.y, t);
        t = fmaf(az, p.z, t);
        return t;
    }
    return CUDART_INF_F;
}

// Part 2: sphere point -> exact NN via center-cluster pruning. 1 warp/query. --
// Candidate list built in shared, then scanned 4 clusters at a time (MLP=4).
__global__ void __launch_bounds__(32*NN_WARPS)
k_nn(const float* __restrict__ sp) {
    __shared__ float4 shc[NCC];    // centers (x,y,z,|c|^2)
    __shared__ int2   shcs[NCC];   // (start, count)
    __shared__ float  shr[NCC];    // padded cluster radius
    __shared__ unsigned short shlist[NN_WARPS][NCC];  // candidate ids per warp
    const int tid  = threadIdx.x;
    const int lane = tid & 31;
    const int warp = tid >> 5;
    const int qblock = blockIdx.x * QPB;
    const int b = qblock / MM;     // QPB divides MM, block never straddles batches

    for (int i = tid; i < NCC; i += 32*NN_WARPS) {
        shc[i]  = g_ctr[b*NCC + i];
        shcs[i] = make_int2(g_start[b*NCC + i], g_cnt[b*NCC + i]);
        shr[i]  = __uint_as_float(g_rmax[b*NCC + i]) * 1.000002f + 1e-6f;
    }
    __syncthreads();

    const float4* __restrict__ pts = g_psort;
    unsigned short* const mylist = shlist[warp];

    for (int qi = 0; qi < QPW; ++qi) {
        const int q = qblock + warp*QPW + qi;       // global sphere-point index
        const float* sq = sp + (long long)q * 3;
        float qx = sq[0], qy = sq[1], qz = sq[2];   // warp-broadcast loads
        float ax = -2.0f*qx, ay = -2.0f*qy, az = -2.0f*qz;
        float qw = qx*qx + qy*qy + qz*qz;

        // Phase A: nearest non-empty center (no dsq storage)
        float tmin = CUDART_INF_F; int tidx = 0;
        #pragma unroll
        for (int k = 0; k < 32; ++k) {
            const int cid = k*32 + lane;
            float4 c = shc[cid];
            float t = fmaf(ax, c.x, c.w);
            t = fmaf(ay, c.y, t);
            t = fmaf(az, c.z, t);
            float tm = (shcs[cid].y > 0) ? t : CUDART_INF_F;
            if (tm < tmin) { tmin = tm; tidx = cid; }
        }
        #pragma unroll
        for (int o = 16; o > 0; o >>= 1) {
            float ot = __shfl_down_sync(0xffffffffu, tmin, o);
            int   oi = __shfl_down_sync(0xffffffffu, tidx, o);
            if (ot < tmin) { tmin = ot; tidx = oi; }
        }
        const int cidx0 = __shfl_sync(0xffffffffu, tidx, 0);

        // Phase B: seed best from nearest non-empty cluster
        float lmin = CUDART_INF_F;
        {
            int2 sc = shcs[cidx0];
            for (int o = lane; o < sc.y; o += 32) {
                float4 p = pts[sc.x + o];
                float t = fmaf(ax, p.x, p.w);
                t = fmaf(ay, p.y, t);
                t = fmaf(az, p.z, t);
                lmin = fminf(lmin, t);
            }
        }
        const float best = sqrtf(fmaxf(warpMin(lmin) + qw, 0.0f));

        // Phase C1: build candidate list (recompute center distances)
        int nc = 0;
        #pragma unroll
        for (int k = 0; k < 32; ++k) {
            const int cid = k*32 + lane;
            float4 c = shc[cid];
            float t = fmaf(ax, c.x, c.w);
            t = fmaf(ay, c.y, t);
            t = fmaf(az, c.z, t);
            float thr = best + shr[cid];
            bool pred = (shcs[cid].y > 0) && (cid != cidx0)
                        && (t + qw < thr*thr);
            unsigned m = __ballot_sync(0xffffffffu, pred);
            if (pred) {
                int off = __popc(m & ((1u << lane) - 1u));
                mylist[nc + off] = (unsigned short)cid;
            }
            nc += __popc(m);
        }
        __syncwarp();

        // Phase C2: scan candidates 4 at a time (4 independent load chains)
        int ci = 0;
        for (; ci + 4 <= nc; ci += 4) {
            int2 s0 = shcs[mylist[ci+0]];
            int2 s1 = shcs[mylist[ci+1]];
            int2 s2 = shcs[mylist[ci+2]];
            int2 s3 = shcs[mylist[ci+3]];
            lmin = fminf(lmin, candTerm(pts, s0.x, s0.y, lane, ax, ay, az));
            lmin = fminf(lmin, candTerm(pts, s1.x, s1.y, lane, ax, ay, az));
            lmin = fminf(lmin, candTerm(pts, s2.x, s2.y, lane, ax, ay, az));
            lmin = fminf(lmin, candTerm(pts, s3.x, s3.y, lane, ax, ay, az));
            int mx = max(max(s0.y, s1.y), max(s2.y, s3.y));
            for (int o = lane + 32; o < mx; o += 32) {
                lmin = fminf(lmin, candTerm(pts, s0.x, s0.y, o, ax, ay, az));
                lmin = fminf(lmin, candTerm(pts, s1.x, s1.y, o, ax, ay, az));
                lmin = fminf(lmin, candTerm(pts, s2.x, s2.y, o, ax, ay, az));
                lmin = fminf(lmin, candTerm(pts, s3.x, s3.y, o, ax, ay, az));
            }
        }
        for (; ci < nc; ++ci) {
            int2 s0 = shcs[mylist[ci]];
            for (int o = lane; o < s0.y; o += 32)
                lmin = fminf(lmin, candTerm(pts, s0.x, s0.y, o, ax, ay, az));
        }

        float best2 = warpMin(lmin) + qw;
        if (lane == 0) g_mind[q] = fmaxf(best2, 0.0f);
    }
}

// Epilogue: one warp per center: max over S, then sum over centers ------------
__global__ void k_c2p() {
    const int lane = threadIdx.x & 31;
    const int wid  = (blockIdx.x * blockDim.x + threadIdx.x) >> 5;  // 0..BB*NCC-1
    float v = sqrtf(fmaxf(g_mind[wid*SS + lane], 1e-12f));
    #pragma unroll
    for (int o = 16; o > 0; o >>= 1)
        v = fmaxf(v, __shfl_xor_sync(0xffffffffu, v, o));
    if (lane == 0) atomicAdd(&g_acc[2 + wid/NCC], v);
}

// Final scalar ----------------------------------------------------------------
__global__ void k_final(float* out) {
    float r = 0.0f;
    #pragma unroll
    for (int b = 0; b < BB; ++b)
        r += g_acc[b] * (1.0f/NN) + g_acc[2 + b] * (1.0f/NCC);
    out[0] = r * (1.0f/BB);
}

// ---------------------------------------------------------------------------
extern "C" void kernel_launch(void* const* d_in, const int* in_sizes, int n_in,
                              void* d_out, int out_size) {
    const float* centers = (const float*)d_in[0];
    const float* radius  = (const float*)d_in[1];
    const float* xyz     = (const float*)d_in[2];
    const float* sp      = (const float*)d_in[3];
    float* out = (float*)d_out;

    k_prep<<<(BB*NN + 255)/256, 256>>>(xyz, centers);
    k_p2c<<<dim3(NN/256, BB), 256>>>(radius);
    k_scan<<<1, 1024>>>();
    k_scatter<<<(BB*NN)/256, 256>>>();
    k_nn<<<(BB*MM)/QPB, 32*NN_WARPS>>>(sp);
    k_c2p<<<dim3((BB*NCC*32)/256), 256>>>();
    k_final<<<1, 1>>>(out);
}